// round 13
// baseline (speedup 1.0000x reference)
#include <cuda_runtime.h>
#include <cuda_bf16.h>
#include <math.h>

// ---------------- scratch (device globals; no allocations allowed) ----------
__device__ unsigned short g_xp   [33554432];   // [B,16,1024,512]
__device__ unsigned short g_xpt  [33554432];   // [B,16,512,1024]
__device__ unsigned short g_cam  [33554432];   // [B,16,512,1024] logits -> conf
__device__ unsigned short g_aff  [33554432];   // [B,16,1024,512]
__device__ unsigned short g_local[16777216];   // [B,16,512,512]
__device__ unsigned short g_g    [16777216];
__device__ unsigned short g_gsum [ 1048576];   // [B,512,512] bin-weighted sum of g
__device__ unsigned short g_query[16777216];   // [B,16,1024,256]
__device__ unsigned short g_oattn[16777216];   // [B,16,1024,256]  (head reused for w2t/Wkg)
__device__ unsigned short g_key  [ 8388608];   // [B,16,512,256]
__device__ unsigned short g_glob [ 1048576];   // [B,512,512]
__device__ unsigned short g_valT [  524288];   // [B,256,512]
__device__ unsigned short g_wbf  [ 1048576];   // packed bf16 weights
__device__ float g_bconf[32768];
__device__ float g_bnS  [512];
__device__ float g_bnT  [512];

#define W_CAM  0
#define W_GCN2 262144
#define W_Q    524288
#define W_K    655360
#define W_V    786432
#define W_OUT  917504

// ---------------- small helpers --------------------------------------------
__device__ __forceinline__ float warpRedSum(float v){
#pragma unroll
    for (int o = 16; o; o >>= 1) v += __shfl_xor_sync(0xffffffffu, v, o);
    return v;
}
__device__ __forceinline__ float warpRedMax(float v){
#pragma unroll
    for (int o = 16; o; o >>= 1) v = fmaxf(v, __shfl_xor_sync(0xffffffffu, v, o));
    return v;
}
__device__ __forceinline__ void mma_bf16(float* d, const unsigned* a, const unsigned* b){
    asm volatile(
        "mma.sync.aligned.m16n8k16.row.col.f32.bf16.bf16.f32 "
        "{%0,%1,%2,%3}, {%4,%5,%6,%7}, {%8,%9}, {%0,%1,%2,%3};"
        : "+f"(d[0]), "+f"(d[1]), "+f"(d[2]), "+f"(d[3])
        : "r"(a[0]), "r"(a[1]), "r"(a[2]), "r"(a[3]), "r"(b[0]), "r"(b[1]));
}
__device__ __forceinline__ void ldsm_x4(unsigned& r0, unsigned& r1,
                                        unsigned& r2, unsigned& r3, unsigned addr){
    asm volatile("ldmatrix.sync.aligned.m8n8.x4.shared.b16 {%0,%1,%2,%3}, [%4];"
                 : "=r"(r0), "=r"(r1), "=r"(r2), "=r"(r3) : "r"(addr));
}
__device__ __forceinline__ void cp16(unsigned saddr, const void* gptr){
    asm volatile("cp.async.cg.shared.global [%0], [%1], 16;"
                 :: "r"(saddr), "l"(gptr) : "memory");
}

// ---------------- BN constant prep ------------------------------------------
__global__ void prep_bn(const float* __restrict__ gam, const float* __restrict__ bet,
                        const float* __restrict__ mean, const float* __restrict__ var,
                        float* __restrict__ S, float* __restrict__ T)
{
    int i = threadIdx.x;
    if (i < 512) {
        float inv = rsqrtf(var[i] + 1e-5f);
        float s = gam[i] * inv;
        S[i] = s;
        T[i] = bet[i] - mean[i] * s;
    }
}

// ---------------- weights fp32 -> bf16 ---------------------------------------
__global__ void cvt_weights(const float* __restrict__ wcam, const float* __restrict__ wgcn2,
                            const float* __restrict__ wq, const float* __restrict__ wk,
                            const float* __restrict__ wv, const float* __restrict__ wout,
                            __nv_bfloat16* __restrict__ dst)
{
    int i = blockIdx.x * blockDim.x + threadIdx.x;   // 0..1048575
    float v;
    if      (i < 262144)  v = wcam [i];
    else if (i < 524288)  v = wgcn2[i - 262144];
    else if (i < 655360)  v = wq   [i - 524288];
    else if (i < 786432)  v = wk   [i - 655360];
    else if (i < 917504)  v = wv   [i - 786432];
    else                  v = wout [i - 917504];
    dst[i] = __float2bfloat16(v);
}

// ---------------- transpose w_gcn2 fp32 [d,c] -> bf16 [c,d] ------------------
__global__ void transpose_w2(const float* __restrict__ w2, __nv_bfloat16* __restrict__ w2t)
{
    __shared__ float t[32][33];
    const int bx = blockIdx.x * 32;   // c block
    const int by = blockIdx.y * 32;   // d block
    const int tx = threadIdx.x, ty = threadIdx.y;
#pragma unroll
    for (int i = 0; i < 4; i++)
        t[ty + 8 * i][tx] = w2[(by + ty + 8 * i) * 512 + bx + tx];   // t[d'][c']
    __syncthreads();
#pragma unroll
    for (int i = 0; i < 4; i++)
        w2t[(bx + ty + 8 * i) * 512 + by + tx] = __float2bfloat16(t[tx][ty + 8 * i]);
}

// ---------------- patch-split transposes -------------------------------------
__global__ void make_xp(const float* __restrict__ x,
                        __nv_bfloat16* __restrict__ xp, __nv_bfloat16* __restrict__ xpt)
{
    __shared__ float t[32][33];
    const int ct = blockIdx.x * 32;
    const int rh = blockIdx.y;
    const int z  = blockIdx.z;            // b*16 + nbin
    const int b  = z >> 4, n = z & 15;
    const int h  = (n >> 2) * 32 + rh;
    const int wb = (n & 3) * 32;
    const int tx = threadIdx.x, ty = threadIdx.y;

    const float* xb = x + ((((long long)b * 512 + ct) * 128 + h) * 128 + wb);
#pragma unroll
    for (int i = 0; i < 4; i++) {
        int cc = ty + 8 * i;
        t[cc][tx] = xb[(long long)cc * 16384 + tx];
    }
    __syncthreads();
    __nv_bfloat16* xpb = xp + (((long long)z * 1024 + rh * 32) * 512) + ct;
#pragma unroll
    for (int i = 0; i < 4; i++) {
        int rw = ty + 8 * i;
        xpb[(long long)rw * 512 + tx] = __float2bfloat16(t[tx][rw]);
    }
    __nv_bfloat16* xptb = xpt + (((long long)z * 512 + ct) * 1024) + rh * 32;
#pragma unroll
    for (int i = 0; i < 4; i++) {
        int cc = ty + 8 * i;
        xptb[(long long)cc * 1024 + tx] = __float2bfloat16(t[cc][tx]);
    }
}

// ---------------- warp-per-row bf16 softmax (in place) -----------------------
// NV uint4 per lane (rowlen = NV*256). 8 warps/block -> 8 rows/block.
// Shuffle-only reductions: no shared memory, no block barriers.
template<bool HASCONF, int NV>
__global__ void softmax_rows_w(__nv_bfloat16* __restrict__ data,
                               float* __restrict__ conf, int rowlen)
{
    const int lane = threadIdx.x & 31;
    const int wid  = threadIdx.x >> 5;
    const long long r = (long long)blockIdx.x * 8 + wid;
    uint4* row = (uint4*)(data + r * (long long)rowlen);

    uint4 v[NV];
    float2 f[NV][4];
    float lmax = -3.402823466e38f, lsum = 0.f;
#pragma unroll
    for (int j = 0; j < NV; j++) {
        v[j] = row[lane + 32 * j];
        f[j][0] = __bfloat1622float2(*(__nv_bfloat162*)&v[j].x);
        f[j][1] = __bfloat1622float2(*(__nv_bfloat162*)&v[j].y);
        f[j][2] = __bfloat1622float2(*(__nv_bfloat162*)&v[j].z);
        f[j][3] = __bfloat1622float2(*(__nv_bfloat162*)&v[j].w);
#pragma unroll
        for (int q = 0; q < 4; q++) {
            lmax = fmaxf(lmax, fmaxf(f[j][q].x, f[j][q].y));
            lsum += f[j][q].x + f[j][q].y;
        }
    }
    const float rmax = warpRedMax(lmax);
    if (HASCONF) {
        const float rsum = warpRedSum(lsum);
        if (lane == 0)
            conf[r] = 1.f / (1.f + expf(-rsum / (float)rowlen));
    }
    float les = 0.f;
#pragma unroll
    for (int j = 0; j < NV; j++)
#pragma unroll
        for (int q = 0; q < 4; q++) {
            f[j][q].x = expf(f[j][q].x - rmax);
            f[j][q].y = expf(f[j][q].y - rmax);
            les += f[j][q].x + f[j][q].y;
        }
    const float inv = 1.f / warpRedSum(les);
#pragma unroll
    for (int j = 0; j < NV; j++) {
        uint4 o;
        __nv_bfloat162 p;
        p = __float22bfloat162_rn(make_float2(f[j][0].x * inv, f[j][0].y * inv)); o.x = *(unsigned*)&p;
        p = __float22bfloat162_rn(make_float2(f[j][1].x * inv, f[j][1].y * inv)); o.y = *(unsigned*)&p;
        p = __float22bfloat162_rn(make_float2(f[j][2].x * inv, f[j][2].y * inv)); o.z = *(unsigned*)&p;
        p = __float22bfloat162_rn(make_float2(f[j][3].x * inv, f[j][3].y * inv)); o.w = *(unsigned*)&p;
        row[lane + 32 * j] = o;
    }
}

// ---------------- GCN 16x16 bin mix + residual relu + fused gsum -------------
// g[b,n,j] = relu(local[b,n,j] + Σ_m w1[n,m]·local[b,m,j]);
// gsum[b,j] = Σ_n wf[n]·g[b,n,j]   (all 16 outputs live in registers)
__global__ void gcn_mix(const __nv_bfloat162* __restrict__ local,
                        const float* __restrict__ w1, const float* __restrict__ wf,
                        __nv_bfloat162* __restrict__ g, __nv_bfloat162* __restrict__ gsum)
{
    __shared__ float w[256];
    __shared__ float wfu[16];
    if (threadIdx.x < 256) w[threadIdx.x] = w1[threadIdx.x];
    if (threadIdx.x < 16)  wfu[threadIdx.x] = wf[threadIdx.x];
    __syncthreads();
    long long j = (long long)blockIdx.x * blockDim.x + threadIdx.x;
    const int b = (int)(j >> 17);
    const long long jj = j & 131071;
    const __nv_bfloat162* base = local + ((long long)b << 21) + jj;
    float2 v[16];
#pragma unroll
    for (int m = 0; m < 16; m++) v[m] = __bfloat1622float2(base[(long long)m << 17]);
    __nv_bfloat162* ob = g + ((long long)b << 21) + jj;
    float gsx = 0.f, gsy = 0.f;
#pragma unroll
    for (int n = 0; n < 16; n++) {
        float sx = v[n].x, sy = v[n].y;
#pragma unroll
        for (int m = 0; m < 16; m++) {
            sx = fmaf(w[n * 16 + m], v[m].x, sx);
            sy = fmaf(w[n * 16 + m], v[m].y, sy);
        }
        sx = fmaxf(sx, 0.f);
        sy = fmaxf(sy, 0.f);
        gsx = fmaf(wfu[n], sx, gsx);
        gsy = fmaf(wfu[n], sy, gsy);
        ob[(long long)n << 17] = __float22bfloat162_rn(make_float2(sx, sy));
    }
    gsum[((long long)b << 17) + jj] = __float22bfloat162_rn(make_float2(gsx, gsy));
}

// ---------------- TN GEMM, bf16, ldmatrix + cp.async 4-stage pipeline --------
// (Round-9 proven config + warp-skewed kk order.) CTA tile 128x128, k-tile 32,
// 4 stages (64KB dyn smem, 2 CTAs/SM). Uniform commit_group every iteration so
// wait_group 2 always proves stage `it` landed. ldmatrix addrs precomputed.
// biasMode: 0 none, 1 per-row, 2 per-col, 3 scalar bias[0] + ReLU.
__global__ __launch_bounds__(256, 2) void gemm_tn_tc(
    const __nv_bfloat16* __restrict__ Ab, const __nv_bfloat16* __restrict__ Bb,
    __nv_bfloat16* __restrict__ Cb,
    int N, int Kd,
    long long sA, long long sB, long long sC, int zdivB,
    const float* __restrict__ bias, int biasMode,
    const float* __restrict__ rowscale, long long sScale,
    int epi,
    const float* __restrict__ resid, const float* __restrict__ bnS,
    const float* __restrict__ bnT, float* __restrict__ outp)
{
    extern __shared__ __align__(16) char dsm[];
    const unsigned aBase = (unsigned)__cvta_generic_to_shared(dsm);
    const unsigned bBase = aBase + 32768;

    const int z = blockIdx.z;
    const __nv_bfloat16* A = Ab + (long long)z * sA;
    const __nv_bfloat16* B = Bb + (long long)(z / zdivB) * sB;

    const int tid  = threadIdx.x;
    const int m0   = blockIdx.y * 128;
    const int n0   = blockIdx.x * 128;

    const int lane = tid & 31;
    const int warp = tid >> 5;
    const int gq   = lane >> 2;
    const int tq   = lane & 3;
    const int m0w  = (warp >> 1) * 32;
    const int n0w  = (warp & 1) * 64;
    const int skew = warp & 1;          // kk order skew per warp

    const int r  = tid >> 1;
    const int kq = tid & 1;
    const int swz = (r >> 1) & 3;
    const int ph0 = (2 * kq)     ^ swz;
    const int ph1 = (2 * kq + 1) ^ swz;
    const __nv_bfloat16* Ag = A + (long long)(m0 + r) * Kd + kq * 16;
    const __nv_bfloat16* Bg = B + (long long)(n0 + r) * Kd + kq * 16;
    const unsigned sOffA0 = (unsigned)((r * 4 + ph0) << 4);
    const unsigned sOffA1 = (unsigned)((r * 4 + ph1) << 4);

    const int mi  = lane >> 3;
    const int wr  = lane & 7;
    const int lrow = (mi & 1) * 8 + wr;
    const int segS = mi >> 1;

    const int T = Kd >> 5;

    auto issue = [&](int it){
        if (it < T) {
            const unsigned sb = (unsigned)((it & 3) * 8192);
            const __nv_bfloat16* ag = Ag + it * 32;
            const __nv_bfloat16* bg = Bg + it * 32;
            cp16(aBase + sb + sOffA0, ag);
            cp16(aBase + sb + sOffA1, ag + 8);
            cp16(bBase + sb + sOffA0, bg);
            cp16(bBase + sb + sOffA1, bg + 8);
        }
        asm volatile("cp.async.commit_group;" ::: "memory");
    };

    issue(0); issue(1); issue(2);

    unsigned aAd[2][2], bAd[2][4];
#pragma unroll
    for (int kk = 0; kk < 2; kk++) {
#pragma unroll
        for (int mt = 0; mt < 2; mt++) {
            const int row = m0w + mt * 16 + lrow;
            const int phys = (2 * kk + segS) ^ ((row >> 1) & 3);
            aAd[kk][mt] = aBase + (unsigned)((row * 4 + phys) << 4);
        }
#pragma unroll
        for (int nt2 = 0; nt2 < 4; nt2++) {
            const int row = n0w + nt2 * 16 + lrow;
            const int phys = (2 * kk + segS) ^ ((row >> 1) & 3);
            bAd[kk][nt2] = bBase + (unsigned)((row * 4 + phys) << 4);
        }
    }

    float acc[2][8][4];
#pragma unroll
    for (int i = 0; i < 2; i++)
#pragma unroll
        for (int j = 0; j < 8; j++)
#pragma unroll
            for (int q = 0; q < 4; q++) acc[i][j][q] = 0.f;

    for (int it = 0; it < T; it++) {
        asm volatile("cp.async.wait_group 2;" ::: "memory");
        __syncthreads();
        issue(it + 3);
        const unsigned sb = (unsigned)((it & 3) * 8192);

#pragma unroll
        for (int kk0 = 0; kk0 < 2; kk0++) {
            const int kk = kk0 ^ skew;    // odd warps process k-halves reversed
            unsigned af[2][4], bf[8][2];
#pragma unroll
            for (int mt = 0; mt < 2; mt++)
                ldsm_x4(af[mt][0], af[mt][1], af[mt][2], af[mt][3],
                        aAd[kk][mt] + sb);
#pragma unroll
            for (int nt2 = 0; nt2 < 4; nt2++) {
                unsigned t0, t1, t2, t3;
                ldsm_x4(t0, t1, t2, t3, bAd[kk][nt2] + sb);
                bf[2 * nt2][0] = t0; bf[2 * nt2 + 1][0] = t1;
                bf[2 * nt2][1] = t2; bf[2 * nt2 + 1][1] = t3;
            }
#pragma unroll
            for (int mt = 0; mt < 2; mt++)
#pragma unroll
                for (int nt = 0; nt < 8; nt++)
                    mma_bf16(acc[mt][nt], af[mt], bf[nt]);
        }
    }

    // ---- epilogue ----
    if (biasMode == 1) {
#pragma unroll
        for (int mt = 0; mt < 2; mt++)
#pragma unroll
            for (int h = 0; h < 2; h++) {
                const float bb = bias[m0 + m0w + mt * 16 + gq + h * 8];
#pragma unroll
                for (int nt = 0; nt < 8; nt++) {
                    acc[mt][nt][h * 2 + 0] += bb;
                    acc[mt][nt][h * 2 + 1] += bb;
                }
            }
    } else if (biasMode == 2) {
#pragma unroll
        for (int nt = 0; nt < 8; nt++) {
            const int c0 = n0 + n0w + nt * 8 + 2 * tq;
            const float b0v = bias[c0], b1v = bias[c0 + 1];
#pragma unroll
            for (int mt = 0; mt < 2; mt++) {
                acc[mt][nt][0] += b0v; acc[mt][nt][1] += b1v;
                acc[mt][nt][2] += b0v; acc[mt][nt][3] += b1v;
            }
        }
    } else if (biasMode == 3) {
        const float bb = bias[0];
#pragma unroll
        for (int mt = 0; mt < 2; mt++)
#pragma unroll
            for (int nt = 0; nt < 8; nt++)
#pragma unroll
                for (int q = 0; q < 4; q++)
                    acc[mt][nt][q] = fmaxf(acc[mt][nt][q] + bb, 0.f);
    }
    if (rowscale) {
        const float* rs = rowscale + (long long)z * sScale;
#pragma unroll
        for (int mt = 0; mt < 2; mt++)
#pragma unroll
            for (int h = 0; h < 2; h++) {
                const float f = rs[m0 + m0w + mt * 16 + gq + h * 8];
#pragma unroll
                for (int nt = 0; nt < 8; nt++) {
                    acc[mt][nt][h * 2 + 0] *= f;
                    acc[mt][nt][h * 2 + 1] *= f;
                }
            }
    }

    if (epi == 0) {
        __nv_bfloat16* C = Cb + (long long)z * sC;
#pragma unroll
        for (int mt = 0; mt < 2; mt++)
#pragma unroll
            for (int h = 0; h < 2; h++) {
                const int row = m0 + m0w + mt * 16 + gq + h * 8;
                __nv_bfloat16* cp = C + (long long)row * N + n0 + n0w + 2 * tq;
#pragma unroll
                for (int nt = 0; nt < 8; nt++)
                    *(__nv_bfloat162*)(cp + nt * 8) =
                        __float22bfloat162_rn(
                            make_float2(acc[mt][nt][h * 2 + 0], acc[mt][nt][h * 2 + 1]));
            }
    } else {
        const int b = z >> 4, nbin = z & 15;
        const int hb = (nbin >> 2) * 32, wb = (nbin & 3) * 32;
#pragma unroll
        for (int mt = 0; mt < 2; mt++)
#pragma unroll
            for (int h2 = 0; h2 < 2; h2++) {
                const int co = m0 + m0w + mt * 16 + gq + h2 * 8;
                const float sc = bnS[co], tt = bnT[co];
                const long long cbase = ((long long)(b * 512 + co) * 128);
#pragma unroll
                for (int nt = 0; nt < 8; nt++) {
                    const int p = n0 + n0w + nt * 8 + 2 * tq;   // even
                    const int hh = hb + (p >> 5);
                    const int ww = wb + (p & 31);
                    const long long oi = (cbase + hh) * 128 + ww;
                    float2 rv = *(const float2*)(resid + oi);
                    float v0 = fmaxf(fmaf(acc[mt][nt][h2 * 2 + 0], sc, tt), 0.f);
                    float v1 = fmaxf(fmaf(acc[mt][nt][h2 * 2 + 1], sc, tt), 0.f);
                    *(float2*)(outp + oi) = make_float2(rv.x + v0, rv.y + v1);
                }
            }
    }
}

// ---------------- host side --------------------------------------------------
#define GEMM_SMEM 65536

static void gemm(const __nv_bfloat16* A, const __nv_bfloat16* B, __nv_bfloat16* C,
                 int M, int N, int Kd,
                 long long sA, long long sB, long long sC, int Z, int zdivB = 1,
                 const float* bias = nullptr, int biasMode = 0,
                 const float* rowscale = nullptr, long long sScale = 0,
                 int epi = 0, const float* resid = nullptr,
                 const float* bnS = nullptr, const float* bnT = nullptr,
                 float* outp = nullptr)
{
    dim3 grid(N / 128, M / 128, Z), block(256);
    gemm_tn_tc<<<grid, block, GEMM_SMEM>>>(A, B, C, N, Kd, sA, sB, sC, zdivB,
                                           bias, biasMode, rowscale, sScale,
                                           epi, resid, bnS, bnT, outp);
}

extern "C" void kernel_launch(void* const* d_in, const int* in_sizes, int n_in,
                              void* d_out, int out_size)
{
    const float* x      = (const float*)d_in[0];
    const float* w_cam  = (const float*)d_in[1];
    const float* b_cam  = (const float*)d_in[2];
    const float* w_gcn1 = (const float*)d_in[3];
    const float* w_gcn2 = (const float*)d_in[4];
    const float* w_fuse = (const float*)d_in[5];
    const float* b_fuse = (const float*)d_in[6];
    const float* w_q    = (const float*)d_in[7];
    const float* b_q    = (const float*)d_in[8];
    const float* w_k    = (const float*)d_in[9];
    const float* b_k    = (const float*)d_in[10];
    const float* w_v    = (const float*)d_in[11];
    const float* b_v    = (const float*)d_in[12];
    const float* w_out  = (const float*)d_in[13];
    const float* bn_g   = (const float*)d_in[14];
    const float* bn_b   = (const float*)d_in[15];
    const float* bn_m   = (const float*)d_in[16];
    const float* bn_v   = (const float*)d_in[17];
    float* out = (float*)d_out;

    cudaFuncSetAttribute(gemm_tn_tc, cudaFuncAttributeMaxDynamicSharedMemorySize,
                         GEMM_SMEM);

    __nv_bfloat16 *xp, *xpt, *cam, *aff, *loc, *gg, *gsum, *qry, *oat, *key, *glob, *valT, *wbf;
    float *bconf, *bnS, *bnT;
    cudaGetSymbolAddress((void**)&xp,    g_xp);
    cudaGetSymbolAddress((void**)&xpt,   g_xpt);
    cudaGetSymbolAddress((void**)&cam,   g_cam);
    cudaGetSymbolAddress((void**)&aff,   g_aff);
    cudaGetSymbolAddress((void**)&loc,   g_local);
    cudaGetSymbolAddress((void**)&gg,    g_g);
    cudaGetSymbolAddress((void**)&gsum,  g_gsum);
    cudaGetSymbolAddress((void**)&qry,   g_query);
    cudaGetSymbolAddress((void**)&oat,   g_oattn);
    cudaGetSymbolAddress((void**)&key,   g_key);
    cudaGetSymbolAddress((void**)&glob,  g_glob);
    cudaGetSymbolAddress((void**)&valT,  g_valT);
    cudaGetSymbolAddress((void**)&wbf,   g_wbf);
    cudaGetSymbolAddress((void**)&bconf, g_bconf);
    cudaGetSymbolAddress((void**)&bnS,   g_bnS);
    cudaGetSymbolAddress((void**)&bnT,   g_bnT);

    // scratch for folded weights at the head of g_oattn (oat written only
    // after aff; w2t/Wkg last read at the key GEMM, which precedes aff)
    __nv_bfloat16* w2t = oat;            // [c=512][d=512]
    __nv_bfloat16* wkg = oat + 262144;   // [i=256][c=512] = w_k @ w_gcn2

    // constants & folded weights
    prep_bn<<<1, 512>>>(bn_g, bn_b, bn_m, bn_v, bnS, bnT);
    cvt_weights<<<4096, 256>>>(w_cam, w_gcn2, w_q, w_k, w_v, w_out, wbf);
    transpose_w2<<<dim3(16, 16), dim3(32, 8)>>>(w_gcn2, w2t);
    gemm(wbf + W_K, w2t, wkg, 256, 512, 512, 0, 0, 0, 1);

    // patch-split transposes (fp32 -> bf16)
    make_xp<<<dim3(16, 32, 64), dim3(32, 8)>>>(x, xp, xpt);

    // cam^T[b,n,k,p] = w_cam @ x_p^T (+b_cam per row k)
    gemm(wbf + W_CAM, xp, cam, 512, 1024, 512, 0, 524288, 524288, 64, 1, b_cam, 1);

    // pixel softmax over p (rowlen 1024, NV=4) + bin_conf = sigmoid(row mean)
    softmax_rows_w<true, 4><<<4096, 256>>>(cam, bconf, 1024);

    // local[b,n,k,c] = (conf^T @ x_p) * bin_conf[k]
    gemm(cam, xpt, loc, 512, 512, 1024, 524288, 524288, 262144, 64, 1,
         nullptr, 0, bconf, 512);

    // GCN bin mix + residual relu + fused gsum
    gcn_mix<<<2048, 256>>>((const __nv_bfloat162*)loc, w_gcn1, w_fuse,
                           (__nv_bfloat162*)gg, (__nv_bfloat162*)gsum);

    // glob = relu(gsum @ w_gcn2^T + b_fuse)
    gemm(gsum, wbf + W_GCN2, glob, 2048, 512, 512, 0, 0, 0, 1, 1, b_fuse, 3);

    // key = g @ (w_k @ w_gcn2)^T + b_k   (lf never materialized)
    gemm(gg, wkg, key, 32768, 256, 512, 0, 0, 0, 1, 1, b_k, 2);

    // query / value^T
    gemm(xp, wbf + W_Q, qry, 65536, 256, 512, 0, 0, 0, 1, 1, b_q, 2);
    gemm(wbf + W_V, glob, valT, 256, 512, 512, 0, 262144, 131072, 4, 1, b_v, 1);

    // aff = query @ key^T per (b,bin); softmax over k (rowlen 512, NV=2)
    gemm(qry, key, aff, 1024, 512, 256, 262144, 131072, 524288, 64);
    softmax_rows_w<false, 2><<<8192, 256>>>(aff, nullptr, 512);

    // out_attn = aff @ value (value shared across bins: zdivB=16)
    gemm(aff, valT, oat, 1024, 256, 512, 524288, 131072, 262144, 64, 16);

    // final 1x1 conv + BN + relu + residual, patch-recover fused epilogue
    gemm(wbf + W_OUT, oat, nullptr, 512, 1024, 256, 0, 262144, 0, 64, 1,
         nullptr, 0, nullptr, 0, 2, x, bnS, bnT, out);
}

// round 14
// speedup vs baseline: 1.0738x; 1.0738x over previous
#include <cuda_runtime.h>
#include <cuda_bf16.h>
#include <math.h>

// ---------------- scratch (device globals; no allocations allowed) ----------
__device__ unsigned short g_xp   [33554432];   // [B,16,1024,512]
__device__ unsigned short g_xpt  [33554432];   // [B,16,512,1024]
__device__ unsigned short g_cam  [33554432];   // [B,16,512,1024] logits -> conf
__device__ unsigned short g_aff  [33554432];   // [B,16,1024,512]
__device__ unsigned short g_local[16777216];   // [B,16,512,512]
__device__ unsigned short g_g    [16777216];
__device__ unsigned short g_gsum [ 1048576];   // [B,512,512] bin-weighted sum of g
__device__ unsigned short g_query[16777216];   // [B,16,1024,256]
__device__ unsigned short g_oattn[16777216];   // [B,16,1024,256]  (head reused for w2t/Wkg)
__device__ unsigned short g_key  [ 8388608];   // [B,16,512,256]
__device__ unsigned short g_glob [ 1048576];   // [B,512,512]
__device__ unsigned short g_valT [  524288];   // [B,256,512]
__device__ unsigned short g_wbf  [ 1048576];   // packed bf16 weights
__device__ float g_bconf[32768];
__device__ float g_bnS  [512];
__device__ float g_bnT  [512];

#define W_CAM  0
#define W_GCN2 262144
#define W_Q    524288
#define W_K    655360
#define W_V    786432
#define W_OUT  917504

// ---------------- small helpers --------------------------------------------
__device__ __forceinline__ float warpRedSum(float v){
#pragma unroll
    for (int o = 16; o; o >>= 1) v += __shfl_xor_sync(0xffffffffu, v, o);
    return v;
}
__device__ __forceinline__ float warpRedMax(float v){
#pragma unroll
    for (int o = 16; o; o >>= 1) v = fmaxf(v, __shfl_xor_sync(0xffffffffu, v, o));
    return v;
}
__device__ __forceinline__ void mma_bf16(float* d, const unsigned* a, const unsigned* b){
    asm volatile(
        "mma.sync.aligned.m16n8k16.row.col.f32.bf16.bf16.f32 "
        "{%0,%1,%2,%3}, {%4,%5,%6,%7}, {%8,%9}, {%0,%1,%2,%3};"
        : "+f"(d[0]), "+f"(d[1]), "+f"(d[2]), "+f"(d[3])
        : "r"(a[0]), "r"(a[1]), "r"(a[2]), "r"(a[3]), "r"(b[0]), "r"(b[1]));
}
__device__ __forceinline__ void ldsm_x4(unsigned& r0, unsigned& r1,
                                        unsigned& r2, unsigned& r3, unsigned addr){
    asm volatile("ldmatrix.sync.aligned.m8n8.x4.shared.b16 {%0,%1,%2,%3}, [%4];"
                 : "=r"(r0), "=r"(r1), "=r"(r2), "=r"(r3) : "r"(addr));
}
__device__ __forceinline__ void cp16(unsigned saddr, const void* gptr){
    asm volatile("cp.async.cg.shared.global [%0], [%1], 16;"
                 :: "r"(saddr), "l"(gptr) : "memory");
}

// ---------------- BN constant prep ------------------------------------------
__global__ void prep_bn(const float* __restrict__ gam, const float* __restrict__ bet,
                        const float* __restrict__ mean, const float* __restrict__ var,
                        float* __restrict__ S, float* __restrict__ T)
{
    int i = threadIdx.x;
    if (i < 512) {
        float inv = rsqrtf(var[i] + 1e-5f);
        float s = gam[i] * inv;
        S[i] = s;
        T[i] = bet[i] - mean[i] * s;
    }
}

// ---------------- weights fp32 -> bf16 ---------------------------------------
__global__ void cvt_weights(const float* __restrict__ wcam, const float* __restrict__ wgcn2,
                            const float* __restrict__ wq, const float* __restrict__ wk,
                            const float* __restrict__ wv, const float* __restrict__ wout,
                            __nv_bfloat16* __restrict__ dst)
{
    int i = blockIdx.x * blockDim.x + threadIdx.x;   // 0..1048575
    float v;
    if      (i < 262144)  v = wcam [i];
    else if (i < 524288)  v = wgcn2[i - 262144];
    else if (i < 655360)  v = wq   [i - 524288];
    else if (i < 786432)  v = wk   [i - 655360];
    else if (i < 917504)  v = wv   [i - 786432];
    else                  v = wout [i - 917504];
    dst[i] = __float2bfloat16(v);
}

// ---------------- transpose w_gcn2 fp32 [d,c] -> bf16 [c,d] ------------------
__global__ void transpose_w2(const float* __restrict__ w2, __nv_bfloat16* __restrict__ w2t)
{
    __shared__ float t[32][33];
    const int bx = blockIdx.x * 32;   // c block
    const int by = blockIdx.y * 32;   // d block
    const int tx = threadIdx.x, ty = threadIdx.y;
#pragma unroll
    for (int i = 0; i < 4; i++)
        t[ty + 8 * i][tx] = w2[(by + ty + 8 * i) * 512 + bx + tx];   // t[d'][c']
    __syncthreads();
#pragma unroll
    for (int i = 0; i < 4; i++)
        w2t[(bx + ty + 8 * i) * 512 + by + tx] = __float2bfloat16(t[tx][ty + 8 * i]);
}

// ---------------- patch-split transposes -------------------------------------
__global__ void make_xp(const float* __restrict__ x,
                        __nv_bfloat16* __restrict__ xp, __nv_bfloat16* __restrict__ xpt)
{
    __shared__ float t[32][33];
    const int ct = blockIdx.x * 32;
    const int rh = blockIdx.y;
    const int z  = blockIdx.z;            // b*16 + nbin
    const int b  = z >> 4, n = z & 15;
    const int h  = (n >> 2) * 32 + rh;
    const int wb = (n & 3) * 32;
    const int tx = threadIdx.x, ty = threadIdx.y;

    const float* xb = x + ((((long long)b * 512 + ct) * 128 + h) * 128 + wb);
#pragma unroll
    for (int i = 0; i < 4; i++) {
        int cc = ty + 8 * i;
        t[cc][tx] = xb[(long long)cc * 16384 + tx];
    }
    __syncthreads();
    __nv_bfloat16* xpb = xp + (((long long)z * 1024 + rh * 32) * 512) + ct;
#pragma unroll
    for (int i = 0; i < 4; i++) {
        int rw = ty + 8 * i;
        xpb[(long long)rw * 512 + tx] = __float2bfloat16(t[tx][rw]);
    }
    __nv_bfloat16* xptb = xpt + (((long long)z * 512 + ct) * 1024) + rh * 32;
#pragma unroll
    for (int i = 0; i < 4; i++) {
        int cc = ty + 8 * i;
        xptb[(long long)cc * 1024 + tx] = __float2bfloat16(t[cc][tx]);
    }
}

// ---------------- warp-per-row bf16 softmax (in place) -----------------------
// NV uint4 per lane (rowlen = NV*256). 8 warps/block -> 8 rows/block.
// Shuffle-only reductions: no shared memory, no block barriers.
template<bool HASCONF, int NV>
__global__ void softmax_rows_w(__nv_bfloat16* __restrict__ data,
                               float* __restrict__ conf, int rowlen)
{
    const int lane = threadIdx.x & 31;
    const int wid  = threadIdx.x >> 5;
    const long long r = (long long)blockIdx.x * 8 + wid;
    uint4* row = (uint4*)(data + r * (long long)rowlen);

    uint4 v[NV];
    float2 f[NV][4];
    float lmax = -3.402823466e38f, lsum = 0.f;
#pragma unroll
    for (int j = 0; j < NV; j++) {
        v[j] = row[lane + 32 * j];
        f[j][0] = __bfloat1622float2(*(__nv_bfloat162*)&v[j].x);
        f[j][1] = __bfloat1622float2(*(__nv_bfloat162*)&v[j].y);
        f[j][2] = __bfloat1622float2(*(__nv_bfloat162*)&v[j].z);
        f[j][3] = __bfloat1622float2(*(__nv_bfloat162*)&v[j].w);
#pragma unroll
        for (int q = 0; q < 4; q++) {
            lmax = fmaxf(lmax, fmaxf(f[j][q].x, f[j][q].y));
            lsum += f[j][q].x + f[j][q].y;
        }
    }
    const float rmax = warpRedMax(lmax);
    if (HASCONF) {
        const float rsum = warpRedSum(lsum);
        if (lane == 0)
            conf[r] = 1.f / (1.f + expf(-rsum / (float)rowlen));
    }
    float les = 0.f;
#pragma unroll
    for (int j = 0; j < NV; j++)
#pragma unroll
        for (int q = 0; q < 4; q++) {
            f[j][q].x = expf(f[j][q].x - rmax);
            f[j][q].y = expf(f[j][q].y - rmax);
            les += f[j][q].x + f[j][q].y;
        }
    const float inv = 1.f / warpRedSum(les);
#pragma unroll
    for (int j = 0; j < NV; j++) {
        uint4 o;
        __nv_bfloat162 p;
        p = __float22bfloat162_rn(make_float2(f[j][0].x * inv, f[j][0].y * inv)); o.x = *(unsigned*)&p;
        p = __float22bfloat162_rn(make_float2(f[j][1].x * inv, f[j][1].y * inv)); o.y = *(unsigned*)&p;
        p = __float22bfloat162_rn(make_float2(f[j][2].x * inv, f[j][2].y * inv)); o.z = *(unsigned*)&p;
        p = __float22bfloat162_rn(make_float2(f[j][3].x * inv, f[j][3].y * inv)); o.w = *(unsigned*)&p;
        row[lane + 32 * j] = o;
    }
}

// ---------------- GCN 16x16 bin mix + residual relu + fused gsum -------------
__global__ void gcn_mix(const __nv_bfloat162* __restrict__ local,
                        const float* __restrict__ w1, const float* __restrict__ wf,
                        __nv_bfloat162* __restrict__ g, __nv_bfloat162* __restrict__ gsum)
{
    __shared__ float w[256];
    __shared__ float wfu[16];
    if (threadIdx.x < 256) w[threadIdx.x] = w1[threadIdx.x];
    if (threadIdx.x < 16)  wfu[threadIdx.x] = wf[threadIdx.x];
    __syncthreads();
    long long j = (long long)blockIdx.x * blockDim.x + threadIdx.x;
    const int b = (int)(j >> 17);
    const long long jj = j & 131071;
    const __nv_bfloat162* base = local + ((long long)b << 21) + jj;
    float2 v[16];
#pragma unroll
    for (int m = 0; m < 16; m++) v[m] = __bfloat1622float2(base[(long long)m << 17]);
    __nv_bfloat162* ob = g + ((long long)b << 21) + jj;
    float gsx = 0.f, gsy = 0.f;
#pragma unroll
    for (int n = 0; n < 16; n++) {
        float sx = v[n].x, sy = v[n].y;
#pragma unroll
        for (int m = 0; m < 16; m++) {
            sx = fmaf(w[n * 16 + m], v[m].x, sx);
            sy = fmaf(w[n * 16 + m], v[m].y, sy);
        }
        sx = fmaxf(sx, 0.f);
        sy = fmaxf(sy, 0.f);
        gsx = fmaf(wfu[n], sx, gsx);
        gsy = fmaf(wfu[n], sy, gsy);
        ob[(long long)n << 17] = __float22bfloat162_rn(make_float2(sx, sy));
    }
    gsum[((long long)b << 17) + jj] = __float22bfloat162_rn(make_float2(gsx, gsy));
}

// ---------------- TN GEMM, bf16, ldmatrix + cp.async 4-stage pipeline --------
// (Round-9/12 proven configuration; uniform kk order.) CTA tile 128x128,
// k-tile 32, 4 stages (64KB dyn smem, 2 CTAs/SM). Uniform commit_group every
// iteration so wait_group 2 proves stage `it` landed. ldmatrix addrs precomputed.
// biasMode: 0 none, 1 per-row, 2 per-col, 3 scalar bias[0] + ReLU.
__global__ __launch_bounds__(256, 2) void gemm_tn_tc(
    const __nv_bfloat16* __restrict__ Ab, const __nv_bfloat16* __restrict__ Bb,
    __nv_bfloat16* __restrict__ Cb,
    int N, int Kd,
    long long sA, long long sB, long long sC, int zdivB,
    const float* __restrict__ bias, int biasMode,
    const float* __restrict__ rowscale, long long sScale,
    int epi,
    const float* __restrict__ resid, const float* __restrict__ bnS,
    const float* __restrict__ bnT, float* __restrict__ outp)
{
    extern __shared__ __align__(16) char dsm[];
    const unsigned aBase = (unsigned)__cvta_generic_to_shared(dsm);
    const unsigned bBase = aBase + 32768;

    const int z = blockIdx.z;
    const __nv_bfloat16* A = Ab + (long long)z * sA;
    const __nv_bfloat16* B = Bb + (long long)(z / zdivB) * sB;

    const int tid  = threadIdx.x;
    const int m0   = blockIdx.y * 128;
    const int n0   = blockIdx.x * 128;

    const int lane = tid & 31;
    const int warp = tid >> 5;
    const int gq   = lane >> 2;
    const int tq   = lane & 3;
    const int m0w  = (warp >> 1) * 32;
    const int n0w  = (warp & 1) * 64;

    const int r  = tid >> 1;
    const int kq = tid & 1;
    const int swz = (r >> 1) & 3;
    const int ph0 = (2 * kq)     ^ swz;
    const int ph1 = (2 * kq + 1) ^ swz;
    const __nv_bfloat16* Ag = A + (long long)(m0 + r) * Kd + kq * 16;
    const __nv_bfloat16* Bg = B + (long long)(n0 + r) * Kd + kq * 16;
    const unsigned sOffA0 = (unsigned)((r * 4 + ph0) << 4);
    const unsigned sOffA1 = (unsigned)((r * 4 + ph1) << 4);

    const int mi  = lane >> 3;
    const int wr  = lane & 7;
    const int lrow = (mi & 1) * 8 + wr;
    const int segS = mi >> 1;

    const int T = Kd >> 5;

    auto issue = [&](int it){
        if (it < T) {
            const unsigned sb = (unsigned)((it & 3) * 8192);
            const __nv_bfloat16* ag = Ag + it * 32;
            const __nv_bfloat16* bg = Bg + it * 32;
            cp16(aBase + sb + sOffA0, ag);
            cp16(aBase + sb + sOffA1, ag + 8);
            cp16(bBase + sb + sOffA0, bg);
            cp16(bBase + sb + sOffA1, bg + 8);
        }
        asm volatile("cp.async.commit_group;" ::: "memory");
    };

    issue(0); issue(1); issue(2);

    unsigned aAd[2][2], bAd[2][4];
#pragma unroll
    for (int kk = 0; kk < 2; kk++) {
#pragma unroll
        for (int mt = 0; mt < 2; mt++) {
            const int row = m0w + mt * 16 + lrow;
            const int phys = (2 * kk + segS) ^ ((row >> 1) & 3);
            aAd[kk][mt] = aBase + (unsigned)((row * 4 + phys) << 4);
        }
#pragma unroll
        for (int nt2 = 0; nt2 < 4; nt2++) {
            const int row = n0w + nt2 * 16 + lrow;
            const int phys = (2 * kk + segS) ^ ((row >> 1) & 3);
            bAd[kk][nt2] = bBase + (unsigned)((row * 4 + phys) << 4);
        }
    }

    float acc[2][8][4];
#pragma unroll
    for (int i = 0; i < 2; i++)
#pragma unroll
        for (int j = 0; j < 8; j++)
#pragma unroll
            for (int q = 0; q < 4; q++) acc[i][j][q] = 0.f;

    for (int it = 0; it < T; it++) {
        asm volatile("cp.async.wait_group 2;" ::: "memory");
        __syncthreads();
        issue(it + 3);
        const unsigned sb = (unsigned)((it & 3) * 8192);

#pragma unroll
        for (int kk = 0; kk < 2; kk++) {
            unsigned af[2][4], bf[8][2];
#pragma unroll
            for (int mt = 0; mt < 2; mt++)
                ldsm_x4(af[mt][0], af[mt][1], af[mt][2], af[mt][3],
                        aAd[kk][mt] + sb);
#pragma unroll
            for (int nt2 = 0; nt2 < 4; nt2++) {
                unsigned t0, t1, t2, t3;
                ldsm_x4(t0, t1, t2, t3, bAd[kk][nt2] + sb);
                bf[2 * nt2][0] = t0; bf[2 * nt2 + 1][0] = t1;
                bf[2 * nt2][1] = t2; bf[2 * nt2 + 1][1] = t3;
            }
#pragma unroll
            for (int mt = 0; mt < 2; mt++)
#pragma unroll
                for (int nt = 0; nt < 8; nt++)
                    mma_bf16(acc[mt][nt], af[mt], bf[nt]);
        }
    }

    // ---- epilogue ----
    if (biasMode == 1) {
#pragma unroll
        for (int mt = 0; mt < 2; mt++)
#pragma unroll
            for (int h = 0; h < 2; h++) {
                const float bb = bias[m0 + m0w + mt * 16 + gq + h * 8];
#pragma unroll
                for (int nt = 0; nt < 8; nt++) {
                    acc[mt][nt][h * 2 + 0] += bb;
                    acc[mt][nt][h * 2 + 1] += bb;
                }
            }
    } else if (biasMode == 2) {
#pragma unroll
        for (int nt = 0; nt < 8; nt++) {
            const int c0 = n0 + n0w + nt * 8 + 2 * tq;
            const float b0v = bias[c0], b1v = bias[c0 + 1];
#pragma unroll
            for (int mt = 0; mt < 2; mt++) {
                acc[mt][nt][0] += b0v; acc[mt][nt][1] += b1v;
                acc[mt][nt][2] += b0v; acc[mt][nt][3] += b1v;
            }
        }
    } else if (biasMode == 3) {
        const float bb = bias[0];
#pragma unroll
        for (int mt = 0; mt < 2; mt++)
#pragma unroll
            for (int nt = 0; nt < 8; nt++)
#pragma unroll
                for (int q = 0; q < 4; q++)
                    acc[mt][nt][q] = fmaxf(acc[mt][nt][q] + bb, 0.f);
    }
    if (rowscale) {
        const float* rs = rowscale + (long long)z * sScale;
#pragma unroll
        for (int mt = 0; mt < 2; mt++)
#pragma unroll
            for (int h = 0; h < 2; h++) {
                const float f = rs[m0 + m0w + mt * 16 + gq + h * 8];
#pragma unroll
                for (int nt = 0; nt < 8; nt++) {
                    acc[mt][nt][h * 2 + 0] *= f;
                    acc[mt][nt][h * 2 + 1] *= f;
                }
            }
    }

    if (epi == 0) {
        __nv_bfloat16* C = Cb + (long long)z * sC;
#pragma unroll
        for (int mt = 0; mt < 2; mt++)
#pragma unroll
            for (int h = 0; h < 2; h++) {
                const int row = m0 + m0w + mt * 16 + gq + h * 8;
                __nv_bfloat16* cp = C + (long long)row * N + n0 + n0w + 2 * tq;
#pragma unroll
                for (int nt = 0; nt < 8; nt++)
                    *(__nv_bfloat162*)(cp + nt * 8) =
                        __float22bfloat162_rn(
                            make_float2(acc[mt][nt][h * 2 + 0], acc[mt][nt][h * 2 + 1]));
            }
    } else {
        const int b = z >> 4, nbin = z & 15;
        const int hb = (nbin >> 2) * 32, wb = (nbin & 3) * 32;
#pragma unroll
        for (int mt = 0; mt < 2; mt++)
#pragma unroll
            for (int h2 = 0; h2 < 2; h2++) {
                const int co = m0 + m0w + mt * 16 + gq + h2 * 8;
                const float sc = bnS[co], tt = bnT[co];
                const long long cbase = ((long long)(b * 512 + co) * 128);
#pragma unroll
                for (int nt = 0; nt < 8; nt++) {
                    const int p = n0 + n0w + nt * 8 + 2 * tq;   // even
                    const int hh = hb + (p >> 5);
                    const int ww = wb + (p & 31);
                    const long long oi = (cbase + hh) * 128 + ww;
                    float2 rv = *(const float2*)(resid + oi);
                    float v0 = fmaxf(fmaf(acc[mt][nt][h2 * 2 + 0], sc, tt), 0.f);
                    float v1 = fmaxf(fmaf(acc[mt][nt][h2 * 2 + 1], sc, tt), 0.f);
                    *(float2*)(outp + oi) = make_float2(rv.x + v0, rv.y + v1);
                }
            }
    }
}

// ---------------- host side --------------------------------------------------
#define GEMM_SMEM 65536

static void gemm(const __nv_bfloat16* A, const __nv_bfloat16* B, __nv_bfloat16* C,
                 int M, int N, int Kd,
                 long long sA, long long sB, long long sC, int Z, int zdivB = 1,
                 const float* bias = nullptr, int biasMode = 0,
                 const float* rowscale = nullptr, long long sScale = 0,
                 int epi = 0, const float* resid = nullptr,
                 const float* bnS = nullptr, const float* bnT = nullptr,
                 float* outp = nullptr)
{
    dim3 grid(N / 128, M / 128, Z), block(256);
    gemm_tn_tc<<<grid, block, GEMM_SMEM>>>(A, B, C, N, Kd, sA, sB, sC, zdivB,
                                           bias, biasMode, rowscale, sScale,
                                           epi, resid, bnS, bnT, outp);
}

extern "C" void kernel_launch(void* const* d_in, const int* in_sizes, int n_in,
                              void* d_out, int out_size)
{
    const float* x      = (const float*)d_in[0];
    const float* w_cam  = (const float*)d_in[1];
    const float* b_cam  = (const float*)d_in[2];
    const float* w_gcn1 = (const float*)d_in[3];
    const float* w_gcn2 = (const float*)d_in[4];
    const float* w_fuse = (const float*)d_in[5];
    const float* b_fuse = (const float*)d_in[6];
    const float* w_q    = (const float*)d_in[7];
    const float* b_q    = (const float*)d_in[8];
    const float* w_k    = (const float*)d_in[9];
    const float* b_k    = (const float*)d_in[10];
    const float* w_v    = (const float*)d_in[11];
    const float* b_v    = (const float*)d_in[12];
    const float* w_out  = (const float*)d_in[13];
    const float* bn_g   = (const float*)d_in[14];
    const float* bn_b   = (const float*)d_in[15];
    const float* bn_m   = (const float*)d_in[16];
    const float* bn_v   = (const float*)d_in[17];
    float* out = (float*)d_out;

    cudaFuncSetAttribute(gemm_tn_tc, cudaFuncAttributeMaxDynamicSharedMemorySize,
                         GEMM_SMEM);

    __nv_bfloat16 *xp, *xpt, *cam, *aff, *loc, *gg, *gsum, *qry, *oat, *key, *glob, *valT, *wbf;
    float *bconf, *bnS, *bnT;
    cudaGetSymbolAddress((void**)&xp,    g_xp);
    cudaGetSymbolAddress((void**)&xpt,   g_xpt);
    cudaGetSymbolAddress((void**)&cam,   g_cam);
    cudaGetSymbolAddress((void**)&aff,   g_aff);
    cudaGetSymbolAddress((void**)&loc,   g_local);
    cudaGetSymbolAddress((void**)&gg,    g_g);
    cudaGetSymbolAddress((void**)&gsum,  g_gsum);
    cudaGetSymbolAddress((void**)&qry,   g_query);
    cudaGetSymbolAddress((void**)&oat,   g_oattn);
    cudaGetSymbolAddress((void**)&key,   g_key);
    cudaGetSymbolAddress((void**)&glob,  g_glob);
    cudaGetSymbolAddress((void**)&valT,  g_valT);
    cudaGetSymbolAddress((void**)&wbf,   g_wbf);
    cudaGetSymbolAddress((void**)&bconf, g_bconf);
    cudaGetSymbolAddress((void**)&bnS,   g_bnS);
    cudaGetSymbolAddress((void**)&bnT,   g_bnT);

    // scratch for folded weights at the head of g_oattn (oat written only
    // after aff; w2t/Wkg last read at the key GEMM, which precedes aff)
    __nv_bfloat16* w2t = oat;            // [c=512][d=512]
    __nv_bfloat16* wkg = oat + 262144;   // [i=256][c=512] = w_k @ w_gcn2

    // constants & folded weights
    prep_bn<<<1, 512>>>(bn_g, bn_b, bn_m, bn_v, bnS, bnT);
    cvt_weights<<<4096, 256>>>(w_cam, w_gcn2, w_q, w_k, w_v, w_out, wbf);
    transpose_w2<<<dim3(16, 16), dim3(32, 8)>>>(w_gcn2, w2t);
    gemm(wbf + W_K, w2t, wkg, 256, 512, 512, 0, 0, 0, 1);

    // patch-split transposes (fp32 -> bf16)
    make_xp<<<dim3(16, 32, 64), dim3(32, 8)>>>(x, xp, xpt);

    // cam^T[b,n,k,p] = w_cam @ x_p^T (+b_cam per row k)
    gemm(wbf + W_CAM, xp, cam, 512, 1024, 512, 0, 524288, 524288, 64, 1, b_cam, 1);

    // pixel softmax over p (rowlen 1024, NV=4) + bin_conf = sigmoid(row mean)
    softmax_rows_w<true, 4><<<4096, 256>>>(cam, bconf, 1024);

    // local[b,n,k,c] = (conf^T @ x_p) * bin_conf[k]
    gemm(cam, xpt, loc, 512, 512, 1024, 524288, 524288, 262144, 64, 1,
         nullptr, 0, bconf, 512);

    // GCN bin mix + residual relu + fused gsum
    gcn_mix<<<2048, 256>>>((const __nv_bfloat162*)loc, w_gcn1, w_fuse,
                           (__nv_bfloat162*)gg, (__nv_bfloat162*)gsum);

    // glob = relu(gsum @ w_gcn2^T + b_fuse)
    gemm(gsum, wbf + W_GCN2, glob, 2048, 512, 512, 0, 0, 0, 1, 1, b_fuse, 3);

    // key = g @ (w_k @ w_gcn2)^T + b_k   (lf never materialized)
    gemm(gg, wkg, key, 32768, 256, 512, 0, 0, 0, 1, 1, b_k, 2);

    // query / value^T
    gemm(xp, wbf + W_Q, qry, 65536, 256, 512, 0, 0, 0, 1, 1, b_q, 2);
    gemm(wbf + W_V, glob, valT, 256, 512, 512, 0, 262144, 131072, 4, 1, b_v, 1);

    // aff = query @ key^T per (b,bin); softmax over k (rowlen 512, NV=2)
    gemm(qry, key, aff, 1024, 512, 256, 262144, 131072, 524288, 64);
    softmax_rows_w<false, 2><<<8192, 256>>>(aff, nullptr, 512);

    // out_attn = aff @ value (value shared across bins: zdivB=16)
    gemm(aff, valT, oat, 1024, 256, 512, 524288, 131072, 262144, 64, 16);

    // final 1x1 conv + BN + relu + residual, patch-recover fused epilogue
    gemm(wbf + W_OUT, oat, nullptr, 512, 1024, 256, 0, 262144, 0, 64, 1,
         nullptr, 0, nullptr, 0, 2, x, bnS, bnT, out);
}